// round 3
// baseline (speedup 1.0000x reference)
#include <cuda_runtime.h>
#include <cuda_pipeline.h>

// Problem constants (fixed by the dataset)
#define BATCH   512
#define IN_DIM  256
#define OUT_DIM 256
#define NROWS   68          // G + K = 64 + 4
#define NT      71          // knot count
#define KORD    4

// Tiling
#define BT 64               // batch rows per block
#define CC 16               // input channels per block
#define NB (BATCH / BT)     // 8 batch tiles
#define NC (IN_DIM / CC)    // 16 c-chunks
#define W_TILE (NROWS * OUT_DIM)   // 17408 floats = 68 KB per buffer
#define NTHREADS 512
#define ROWS_PER_THREAD 8   // BT / (NTHREADS/64)

#define SMEM_BYTES ((CC*BT)*16 + (CC*BT)*8 + 2*W_TILE*4)   // 163840 B

__global__ void __launch_bounds__(256, 1)
zero_out_kernel(float* __restrict__ out, int n)
{
    int i = blockIdx.x * blockDim.x + threadIdx.x;
    if (i < n) out[i] = 0.0f;
}

__global__ void __launch_bounds__(NTHREADS, 1)
kan_main_kernel(const float* __restrict__ x,
                const float* __restrict__ w,
                const float* __restrict__ t,
                float* __restrict__ out)
{
    extern __shared__ float smem[];
    float4* s_n4 = (float4*)smem;                    // [CC*BT] spline basis N0..N3
    float2* s_ms = (float2*)(s_n4 + CC*BT);          // [CC*BT] {silu, base_as_int}
    float*  s_w  = (float*)(s_ms + CC*BT);           // [2][W_TILE] double-buffered w tile

    const int tid = threadIdx.x;
    const int og  = tid & 63;          // output group: columns [4*og, 4*og+4)
    const int bq  = tid >> 6;          // batch octet: rows [8*bq, 8*bq+8)
    const int b0  = blockIdx.x * BT;
    const int c0  = blockIdx.y * CC;

    // ---- prefetch first w tile (channel c0) into buffer 0 via cp.async ----
    {
        const int c = c0;
        for (int j = tid; j < NROWS * (OUT_DIM / 4); j += NTHREADS) {
            int r = j >> 6;        // row 0..67
            int q = j & 63;        // float4 within row
            __pipeline_memcpy_async(
                (float4*)(s_w + r * OUT_DIM) + q,
                (const float4*)(w + (size_t)(r * IN_DIM + c) * OUT_DIM) + q,
                16);
        }
        __pipeline_commit();
    }

    // ---- basis coefficients for this block's (c, b) pairs ----
    for (int e = tid; e < CC * BT; e += NTHREADS) {
        int cl = e >> 6;              // local channel
        int bl = e & 63;              // local batch row
        int c = c0 + cl;
        int b = b0 + bl;
        float xv = __ldg(x + (size_t)b * IN_DIM + c);

        // searchsorted(t, xv, side='right') - 1, clipped to [k-1, NT-k-1]
        int lo = 0, hi = NT;
        while (lo < hi) {
            int mid = (lo + hi) >> 1;
            if (__ldg(t + mid) <= xv) lo = mid + 1; else hi = mid;
        }
        int i = lo - 1;
        i = i < (KORD - 1) ? (KORD - 1) : i;
        i = i > (NT - KORD - 1) ? (NT - KORD - 1) : i;

        float tv0 = __ldg(t + i - 2);
        float tv1 = __ldg(t + i - 1);
        float tv2 = __ldg(t + i);
        float tv3 = __ldg(t + i + 1);
        float tv4 = __ldg(t + i + 2);
        float tv5 = __ldg(t + i + 3);

        float L1 = xv - tv2;
        float L2 = xv - tv1;
        float L3 = xv - tv0;
        float R1 = tv3 - xv;
        float R2 = tv4 - xv;
        float R3 = tv5 - xv;

        // Cox-de Boor, k = 4 (matches reference recurrence in fp32)
        float temp, saved;
        temp = 1.0f / (R1 + L1);
        float n0 = R1 * temp;
        float n1 = L1 * temp;
        temp = n0 / (R1 + L2);
        float m0 = R1 * temp;
        saved = L2 * temp;
        temp = n1 / (R2 + L1);
        float m1 = saved + R2 * temp;
        float m2 = L1 * temp;
        temp = m0 / (R1 + L3);
        float q0 = R1 * temp;
        saved = L3 * temp;
        temp = m1 / (R2 + L2);
        float q1 = saved + R2 * temp;
        saved = L2 * temp;
        temp = m2 / (R3 + L1);
        float q2 = saved + R3 * temp;
        float q3 = L1 * temp;

        float silu = xv / (1.0f + expf(-xv));

        s_n4[e] = make_float4(q0, q1, q2, q3);
        s_ms[e] = make_float2(silu, __int_as_float(i - (KORD - 1)));
    }

    // ---- main loop over channels with double-buffered w tiles ----
    float4 acc[ROWS_PER_THREAD];
#pragma unroll
    for (int i = 0; i < ROWS_PER_THREAD; i++) acc[i] = make_float4(0.f, 0.f, 0.f, 0.f);

    for (int ci = 0; ci < CC; ci++) {
        if (ci + 1 < CC) {
            const int c = c0 + ci + 1;
            float* dbuf = s_w + ((ci + 1) & 1) * W_TILE;
            for (int j = tid; j < NROWS * (OUT_DIM / 4); j += NTHREADS) {
                int r = j >> 6;
                int q = j & 63;
                __pipeline_memcpy_async(
                    (float4*)(dbuf + r * OUT_DIM) + q,
                    (const float4*)(w + (size_t)(r * IN_DIM + c) * OUT_DIM) + q,
                    16);
            }
            __pipeline_commit();
            __pipeline_wait_prior(1);   // current tile complete
        } else {
            __pipeline_wait_prior(0);
        }
        __syncthreads();

        const float4* wb4 = (const float4*)(s_w + (ci & 1) * W_TILE);
        const float4  w67 = wb4[67 * (OUT_DIM / 4) + og];   // silu row hoisted
        const float4* n4  = s_n4 + ci * BT + bq * ROWS_PER_THREAD;
        const float2* ms2 = s_ms + ci * BT + bq * ROWS_PER_THREAD;

#pragma unroll
        for (int i = 0; i < ROWS_PER_THREAD; i++) {
            float4 n  = n4[i];                       // broadcast LDS
            float2 ms = ms2[i];                      // broadcast LDS
            int base = __float_as_int(ms.y);
            const float4* p = wb4 + base * (OUT_DIM / 4) + og;
            float4 f0 = p[0 * (OUT_DIM / 4)];
            float4 f1 = p[1 * (OUT_DIM / 4)];
            float4 f2 = p[2 * (OUT_DIM / 4)];
            float4 f3 = p[3 * (OUT_DIM / 4)];
            float4 a = acc[i];
            a.x = fmaf(n.x, f0.x, a.x); a.y = fmaf(n.x, f0.y, a.y);
            a.z = fmaf(n.x, f0.z, a.z); a.w = fmaf(n.x, f0.w, a.w);
            a.x = fmaf(n.y, f1.x, a.x); a.y = fmaf(n.y, f1.y, a.y);
            a.z = fmaf(n.y, f1.z, a.z); a.w = fmaf(n.y, f1.w, a.w);
            a.x = fmaf(n.z, f2.x, a.x); a.y = fmaf(n.z, f2.y, a.y);
            a.z = fmaf(n.z, f2.z, a.z); a.w = fmaf(n.z, f2.w, a.w);
            a.x = fmaf(n.w, f3.x, a.x); a.y = fmaf(n.w, f3.y, a.y);
            a.z = fmaf(n.w, f3.z, a.z); a.w = fmaf(n.w, f3.w, a.w);
            a.x = fmaf(ms.x, w67.x, a.x); a.y = fmaf(ms.x, w67.y, a.y);
            a.z = fmaf(ms.x, w67.z, a.z); a.w = fmaf(ms.x, w67.w, a.w);
            acc[i] = a;
        }
        __syncthreads();   // protect buffer reuse by next prefetch
    }

    // ---- combine partials across c-chunks ----
#pragma unroll
    for (int i = 0; i < ROWS_PER_THREAD; i++) {
        float* dst = out + (size_t)(b0 + bq * ROWS_PER_THREAD + i) * OUT_DIM + og * 4;
        atomicAdd(dst + 0, acc[i].x);
        atomicAdd(dst + 1, acc[i].y);
        atomicAdd(dst + 2, acc[i].z);
        atomicAdd(dst + 3, acc[i].w);
    }
}

extern "C" void kernel_launch(void* const* d_in, const int* in_sizes, int n_in,
                              void* d_out, int out_size)
{
    const float* x = (const float*)d_in[0];
    const float* w = (const float*)d_in[1];
    const float* t = (const float*)d_in[2];
    float* out = (float*)d_out;

    cudaFuncSetAttribute(kan_main_kernel,
                         cudaFuncAttributeMaxDynamicSharedMemorySize, SMEM_BYTES);

    zero_out_kernel<<<(out_size + 255) / 256, 256>>>(out, out_size);

    dim3 grid(NB, NC);
    kan_main_kernel<<<grid, NTHREADS, SMEM_BYTES>>>(x, w, t, out);
}